// round 7
// baseline (speedup 1.0000x reference)
#include <cuda_runtime.h>
#include <cstdint>

// Problem constants
#define Bv 2
#define Sv 2048
#define Dv 768
#define Hv 12
#define HDv 64
#define Mv (Bv * Sv)   // 4096

// Scratch (device globals: allocation-free rule)
__device__ float    g_qh[Mv * Dv];    // tf32-bit floats
__device__ float    g_kh[Mv * Dv];
__device__ float    g_vh[Mv * Dv];
__device__ float    g_ctx[Mv * Dv];   // tf32-bit floats
__device__ uint32_t g_qc[Mv * Dv];    // pre-converted tf32 inputs
__device__ uint32_t g_kc[Mv * Dv];
__device__ uint32_t g_vc[Mv * Dv];
__device__ uint32_t g_Wqc[Dv * Dv];
__device__ uint32_t g_Wkc[Dv * Dv];
__device__ uint32_t g_Wvc[Dv * Dv];
__device__ uint32_t g_Woc[Dv * Dv];

// ---------------------------------------------------------------------------
// helpers
// ---------------------------------------------------------------------------
__device__ __forceinline__ uint32_t f2tf32(float x) {
    uint32_t u;
    asm("cvt.rna.tf32.f32 %0, %1;" : "=r"(u) : "f"(x));
    return u;
}

__device__ __forceinline__ float ex2(float x) {
    float y;
    asm("ex2.approx.ftz.f32 %0, %1;" : "=f"(y) : "f"(x));
    return y;
}

__device__ __forceinline__ void mma_tf32(float* d, const uint32_t* a, const uint32_t* b) {
    asm volatile(
        "mma.sync.aligned.m16n8k8.row.col.f32.tf32.tf32.f32 "
        "{%0,%1,%2,%3},{%4,%5,%6,%7},{%8,%9},{%0,%1,%2,%3};"
        : "+f"(d[0]), "+f"(d[1]), "+f"(d[2]), "+f"(d[3])
        : "r"(a[0]), "r"(a[1]), "r"(a[2]), "r"(a[3]), "r"(b[0]), "r"(b[1]));
}

__device__ __forceinline__ void cp16(void* dst, const void* src) {
    uint32_t d = (uint32_t)__cvta_generic_to_shared(dst);
    asm volatile("cp.async.cg.shared.global [%0], [%1], 16;" :: "r"(d), "l"(src));
}
#define CP_COMMIT asm volatile("cp.async.commit_group;" ::: "memory")
#define CP_WAIT1  asm volatile("cp.async.wait_group 1;" ::: "memory")

// ---------------------------------------------------------------------------
// tf32 pre-conversion kernels
// ---------------------------------------------------------------------------
__global__ void cvt3_kernel(const float4* __restrict__ a, const float4* __restrict__ b,
                            const float4* __restrict__ c,
                            uint4* __restrict__ oa, uint4* __restrict__ ob,
                            uint4* __restrict__ oc, int n4)
{
    const int i = blockIdx.x * 256 + threadIdx.x;
    if (i >= n4) return;
    const float4* s = (blockIdx.y == 0) ? a : (blockIdx.y == 1) ? b : c;
    uint4*        d = (blockIdx.y == 0) ? oa : (blockIdx.y == 1) ? ob : oc;
    float4 v = s[i];
    uint4 o;
    o.x = f2tf32(v.x); o.y = f2tf32(v.y); o.z = f2tf32(v.z); o.w = f2tf32(v.w);
    d[i] = o;
}

__global__ void cvt4_kernel(const float4* __restrict__ a, const float4* __restrict__ b,
                            const float4* __restrict__ c, const float4* __restrict__ e,
                            uint4* __restrict__ oa, uint4* __restrict__ ob,
                            uint4* __restrict__ oc, uint4* __restrict__ oe, int n4)
{
    const int i = blockIdx.x * 256 + threadIdx.x;
    if (i >= n4) return;
    const float4* s = (blockIdx.y == 0) ? a : (blockIdx.y == 1) ? b : (blockIdx.y == 2) ? c : e;
    uint4*        d = (blockIdx.y == 0) ? oa : (blockIdx.y == 1) ? ob : (blockIdx.y == 2) ? oc : oe;
    float4 v = s[i];
    uint4 o;
    o.x = f2tf32(v.x); o.y = f2tf32(v.y); o.z = f2tf32(v.z); o.w = f2tf32(v.w);
    d[i] = o;
}

// ---------------------------------------------------------------------------
// tf32 GEMM: C[M,N] = A[M,K] @ W[K,N] + bias, inputs pre-converted tf32 bits.
// Block 128x128, 128 threads (4 warps), warp tile 64x64, K-tile 32,
// 2-stage cp.async double buffer. Dynamic smem = 70656 B.
// SPLIT_TF32: headsplit output layout + store tf32 bits.
// ---------------------------------------------------------------------------
#define GEMM_SMEM ((2 * 128 * 36 + 2 * 32 * 132) * 4)

template <bool SPLIT_TF32>
__device__ __forceinline__ void gemm_body(
    const uint32_t* __restrict__ A, const uint32_t* __restrict__ W,
    const float* __restrict__ bias, float* __restrict__ out)
{
    extern __shared__ uint32_t dsm[];
    uint32_t (*As)[128][36] = (uint32_t(*)[128][36])dsm;                 // [2][128][36]
    uint32_t (*Bs)[32][132] = (uint32_t(*)[32][132])(dsm + 2 * 128 * 36);

    const int tid  = threadIdx.x;
    const int lane = tid & 31;
    const int warp = tid >> 5;
    const int gid  = lane >> 2;
    const int tig  = lane & 3;
    const int wm   = (warp & 1) * 64;
    const int wn   = (warp >> 1) * 64;
    const int row0 = blockIdx.y * 128;
    const int col0 = blockIdx.x * 128;

    auto issue = [&](int kt, int s) {
#pragma unroll
        for (int it = 0; it < 8; it++) {
            const int c = it * 128 + tid;
            const int r = c >> 3, u = (c & 7) * 4;
            cp16(&As[s][r][u], A + (size_t)(row0 + r) * Dv + kt * 32 + u);
        }
#pragma unroll
        for (int it = 0; it < 8; it++) {
            const int c = it * 128 + tid;
            const int r = c >> 5, u = (c & 31) * 4;
            cp16(&Bs[s][r][u], W + (size_t)(kt * 32 + r) * Dv + col0 + u);
        }
    };

    float acc[4][8][4] = {};

    issue(0, 0); CP_COMMIT;
    issue(1, 1); CP_COMMIT;

    const int NT = Dv / 32;  // 24
    for (int kt = 0; kt < NT; kt++) {
        CP_WAIT1;
        __syncthreads();
        const int s = kt & 1;
#pragma unroll
        for (int ks = 0; ks < 4; ks++) {
            uint32_t af[4][4], bf[8][2];
            const int kk = ks * 8 + tig;
#pragma unroll
            for (int mt = 0; mt < 4; mt++) {
                const int m = wm + mt * 16 + gid;
                af[mt][0] = As[s][m][kk];
                af[mt][1] = As[s][m + 8][kk];
                af[mt][2] = As[s][m][kk + 4];
                af[mt][3] = As[s][m + 8][kk + 4];
            }
#pragma unroll
            for (int nt = 0; nt < 8; nt++) {
                const int n = wn + nt * 8 + gid;
                bf[nt][0] = Bs[s][kk][n];
                bf[nt][1] = Bs[s][kk + 4][n];
            }
#pragma unroll
            for (int mt = 0; mt < 4; mt++)
#pragma unroll
                for (int nt = 0; nt < 8; nt++)
                    mma_tf32(acc[mt][nt], af[mt], bf[nt]);
        }
        __syncthreads();
        if (kt + 2 < NT) issue(kt + 2, s);
        CP_COMMIT;
    }

    // epilogue
#pragma unroll
    for (int mt = 0; mt < 4; mt++) {
        const int r0 = row0 + wm + mt * 16 + gid;
        const int r1 = r0 + 8;
#pragma unroll
        for (int nt = 0; nt < 8; nt++) {
            const float* d = acc[mt][nt];
            const int n = col0 + wn + nt * 8 + 2 * tig;
            const float b0 = bias[n];
            const float b1 = bias[n + 1];
            if (SPLIT_TF32) {
                const int hh = n >> 6;
                const int hd = n & 63;
                float2 v0, v1;
                v0.x = __uint_as_float(f2tf32(d[0] + b0));
                v0.y = __uint_as_float(f2tf32(d[1] + b1));
                v1.x = __uint_as_float(f2tf32(d[2] + b0));
                v1.y = __uint_as_float(f2tf32(d[3] + b1));
                {
                    const int bb = r0 >> 11, ss = r0 & 2047;
                    *(float2*)&out[(((size_t)(bb * Hv + hh) * Sv) + ss) * HDv + hd] = v0;
                }
                {
                    const int bb = r1 >> 11, ss = r1 & 2047;
                    *(float2*)&out[(((size_t)(bb * Hv + hh) * Sv) + ss) * HDv + hd] = v1;
                }
            } else {
                *(float2*)&out[(size_t)r0 * Dv + n] = make_float2(d[0] + b0, d[1] + b1);
                *(float2*)&out[(size_t)r1 * Dv + n] = make_float2(d[2] + b0, d[3] + b1);
            }
        }
    }
}

__global__ __launch_bounds__(128) void gemm_qkv_kernel(
    const uint32_t* __restrict__ q, const uint32_t* __restrict__ k, const uint32_t* __restrict__ v,
    const uint32_t* __restrict__ Wq, const uint32_t* __restrict__ Wk, const uint32_t* __restrict__ Wv,
    const float* __restrict__ bq, const float* __restrict__ bk, const float* __restrict__ bv,
    float* __restrict__ qh, float* __restrict__ kh, float* __restrict__ vh)
{
    const int z = blockIdx.z;
    const uint32_t* A    = (z == 0) ? q  : (z == 1) ? k  : v;
    const uint32_t* W    = (z == 0) ? Wq : (z == 1) ? Wk : Wv;
    const float*    bias = (z == 0) ? bq : (z == 1) ? bk : bv;
    float*          out  = (z == 0) ? qh : (z == 1) ? kh : vh;
    gemm_body<true>(A, W, bias, out);
}

__global__ __launch_bounds__(128) void gemm_out_kernel(
    const uint32_t* __restrict__ A, const uint32_t* __restrict__ W,
    const float* __restrict__ bias, float* __restrict__ out)
{
    gemm_body<false>(A, W, bias, out);
}

// ---------------------------------------------------------------------------
// tf32 causal flash attention — BM=64 for occupancy.
// Grid (32, B*H), 128 threads (4 warps), warp-M=16, BN=32 keys/tile.
// 2-stage cp.async double buffer; 4 CTAs/SM target (launch_bounds(128,4)).
// Dynamic smem: sK[2][32][68], sV[2][32][76], sP[64][36] = 46080 B.
// ---------------------------------------------------------------------------
#define LOG2E 1.4426950408889634f
#define ATTN_SMEM ((2 * 32 * 68 + 2 * 32 * 76 + 64 * 36) * 4)

__global__ __launch_bounds__(128, 4) void attn_mma_kernel(
    const float* __restrict__ qh, const float* __restrict__ kh,
    const float* __restrict__ vh, float* __restrict__ ctx)
{
    extern __shared__ uint32_t dynsm[];
    uint32_t (*sK)[32][68] = (uint32_t(*)[32][68])dynsm;                     // [2][32][68]
    uint32_t (*sV)[32][76] = (uint32_t(*)[32][76])(dynsm + 2 * 32 * 68);     // [2][32][76]
    uint32_t (*sP)[36]     = (uint32_t(*)[36])(dynsm + 2 * 32 * 68 + 2 * 32 * 76); // [64][36]

    const int tid  = threadIdx.x;
    const int lane = tid & 31;
    const int warp = tid >> 5;
    const int gid  = lane >> 2;
    const int tig  = lane & 3;
    const int wm   = warp * 16;

    const int qt = (gridDim.x - 1) - blockIdx.x;  // long blocks first
    const int bh = blockIdx.y;
    const int b  = bh / Hv;
    const int hd = bh % Hv;

    const float* qb = qh + ((size_t)bh * Sv + qt * 64) * 64;
    const float* kb = kh + (size_t)bh * Sv * 64;
    const float* vb = vh + (size_t)bh * Sv * 64;

    // Q fragments: 8 ksteps x 4 regs (rows wm+gid, wm+gid+8)
    const float SC = 0.125f * LOG2E;
    uint32_t qa[8][4];
#pragma unroll
    for (int ks = 0; ks < 8; ks++) {
        const int r = wm + gid;
        qa[ks][0] = f2tf32(qb[r * 64 + ks * 8 + tig] * SC);
        qa[ks][1] = f2tf32(qb[(r + 8) * 64 + ks * 8 + tig] * SC);
        qa[ks][2] = f2tf32(qb[r * 64 + ks * 8 + tig + 4] * SC);
        qa[ks][3] = f2tf32(qb[(r + 8) * 64 + ks * 8 + tig + 4] * SC);
    }

    float m0 = -1e30f, m1 = -1e30f, l0 = 0.f, l1 = 0.f;
    float o[8][4] = {};

    auto issueKV = [&](int jt, int s) {
        const float* kp = kb + (size_t)jt * 32 * 64;
        const float* vp = vb + (size_t)jt * 32 * 64;
#pragma unroll
        for (int it = 0; it < 4; it++) {
            const int c = it * 128 + tid;
            const int r = c >> 4, u = (c & 15) * 4;
            cp16(&sK[s][r][u], kp + r * 64 + u);
            cp16(&sV[s][r][u], vp + r * 64 + u);
        }
    };

    const int ntiles = 2 * qt + 2;
    issueKV(0, 0); CP_COMMIT;
    issueKV(1, 1); CP_COMMIT;

    for (int jt = 0; jt < ntiles; jt++) {
        CP_WAIT1;
        __syncthreads();
        const int s = jt & 1;

        if (jt * 32 <= qt * 64 + wm + 15) {  // warp has unmasked rows in this tile
            // ---- QK^T ----
            float sacc[4][4] = {};
#pragma unroll
            for (int ks = 0; ks < 8; ks++) {
                const int kk = ks * 8 + tig;
#pragma unroll
                for (int nt = 0; nt < 4; nt++) {
                    uint32_t bf[2];
                    bf[0] = sK[s][nt * 8 + gid][kk];
                    bf[1] = sK[s][nt * 8 + gid][kk + 4];
                    mma_tf32(sacc[nt], qa[ks], bf);
                }
            }

            // ---- causal mask (diagonal region only) ----
            if (jt >= 2 * qt) {
                const int ig = qt * 64 + wm + gid;
#pragma unroll
                for (int nt = 0; nt < 4; nt++) {
                    const int jg = jt * 32 + nt * 8 + 2 * tig;
                    if (jg > ig)         sacc[nt][0] = -1e30f;
                    if (jg + 1 > ig)     sacc[nt][1] = -1e30f;
                    if (jg > ig + 8)     sacc[nt][2] = -1e30f;
                    if (jg + 1 > ig + 8) sacc[nt][3] = -1e30f;
                }
            }

            // ---- online softmax (log2 domain) ----
            float mx0 = -1e30f, mx1 = -1e30f;
#pragma unroll
            for (int nt = 0; nt < 4; nt++) {
                mx0 = fmaxf(mx0, fmaxf(sacc[nt][0], sacc[nt][1]));
                mx1 = fmaxf(mx1, fmaxf(sacc[nt][2], sacc[nt][3]));
            }
            mx0 = fmaxf(mx0, __shfl_xor_sync(0xffffffffu, mx0, 1));
            mx0 = fmaxf(mx0, __shfl_xor_sync(0xffffffffu, mx0, 2));
            mx1 = fmaxf(mx1, __shfl_xor_sync(0xffffffffu, mx1, 1));
            mx1 = fmaxf(mx1, __shfl_xor_sync(0xffffffffu, mx1, 2));

            const float nm0 = fmaxf(m0, mx0);
            const float nm1 = fmaxf(m1, mx1);
            const float a0 = ex2(m0 - nm0);
            const float a1 = ex2(m1 - nm1);
            m0 = nm0; m1 = nm1;

            const int r = wm + gid;
            float ps0 = 0.f, ps1 = 0.f;
#pragma unroll
            for (int nt = 0; nt < 4; nt++) {
                const float p00 = ex2(sacc[nt][0] - nm0);
                const float p01 = ex2(sacc[nt][1] - nm0);
                const float p10 = ex2(sacc[nt][2] - nm1);
                const float p11 = ex2(sacc[nt][3] - nm1);
                ps0 += p00 + p01;
                ps1 += p10 + p11;
                uint2 t;
                t.x = f2tf32(p00); t.y = f2tf32(p01);
                *(uint2*)&sP[r][nt * 8 + 2 * tig] = t;
                t.x = f2tf32(p10); t.y = f2tf32(p11);
                *(uint2*)&sP[r + 8][nt * 8 + 2 * tig] = t;
            }
            ps0 += __shfl_xor_sync(0xffffffffu, ps0, 1);
            ps0 += __shfl_xor_sync(0xffffffffu, ps0, 2);
            ps1 += __shfl_xor_sync(0xffffffffu, ps1, 1);
            ps1 += __shfl_xor_sync(0xffffffffu, ps1, 2);
            l0 = l0 * a0 + ps0;
            l1 = l1 * a1 + ps1;

#pragma unroll
            for (int nt = 0; nt < 8; nt++) {
                o[nt][0] *= a0; o[nt][1] *= a0;
                o[nt][2] *= a1; o[nt][3] *= a1;
            }
            __syncwarp();

            // ---- P @ V ----
#pragma unroll
            for (int ks = 0; ks < 4; ks++) {
                const int kk = ks * 8 + tig;
                uint32_t pa[4];
                pa[0] = sP[r][kk];
                pa[1] = sP[r + 8][kk];
                pa[2] = sP[r][kk + 4];
                pa[3] = sP[r + 8][kk + 4];
#pragma unroll
                for (int nt = 0; nt < 8; nt++) {
                    uint32_t bf[2];
                    bf[0] = sV[s][kk][nt * 8 + gid];
                    bf[1] = sV[s][kk + 4][nt * 8 + gid];
                    mma_tf32(o[nt], pa, bf);
                }
            }
        }

        __syncthreads();
        if (jt + 2 < ntiles) issueKV(jt + 2, s);
        CP_COMMIT;
    }

    // ---- epilogue: normalize, write ctx as tf32 bits ----
    const float il0 = 1.f / l0;
    const float il1 = 1.f / l1;
    const int r0 = qt * 64 + wm + gid;
    float* ob0 = ctx + ((size_t)(b * Sv + r0)) * Dv + hd * 64;
    float* ob1 = ctx + ((size_t)(b * Sv + r0 + 8)) * Dv + hd * 64;
#pragma unroll
    for (int nt = 0; nt < 8; nt++) {
        uint2 w;
        w.x = f2tf32(o[nt][0] * il0);
        w.y = f2tf32(o[nt][1] * il0);
        *(uint2*)&ob0[nt * 8 + 2 * tig] = w;
        w.x = f2tf32(o[nt][2] * il1);
        w.y = f2tf32(o[nt][3] * il1);
        *(uint2*)&ob1[nt * 8 + 2 * tig] = w;
    }
}

// ---------------------------------------------------------------------------
extern "C" void kernel_launch(void* const* d_in, const int* in_sizes, int n_in,
                              void* d_out, int out_size)
{
    const float* q  = (const float*)d_in[0];
    const float* k  = (const float*)d_in[1];
    const float* v  = (const float*)d_in[2];
    // d_in[3] = mask (causal, implemented directly)
    const float* Wq = (const float*)d_in[4];
    const float* bq = (const float*)d_in[5];
    const float* Wk = (const float*)d_in[6];
    const float* bk = (const float*)d_in[7];
    const float* Wv = (const float*)d_in[8];
    const float* bv = (const float*)d_in[9];
    const float* Wo = (const float*)d_in[10];
    const float* bo = (const float*)d_in[11];
    float* out = (float*)d_out;

    void *p_qh, *p_kh, *p_vh, *p_ctx, *p_qc, *p_kc, *p_vc, *p_wq, *p_wk, *p_wv, *p_wo;
    cudaGetSymbolAddress(&p_qh, g_qh);
    cudaGetSymbolAddress(&p_kh, g_kh);
    cudaGetSymbolAddress(&p_vh, g_vh);
    cudaGetSymbolAddress(&p_ctx, g_ctx);
    cudaGetSymbolAddress(&p_qc, g_qc);
    cudaGetSymbolAddress(&p_kc, g_kc);
    cudaGetSymbolAddress(&p_vc, g_vc);
    cudaGetSymbolAddress(&p_wq, g_Wqc);
    cudaGetSymbolAddress(&p_wk, g_Wkc);
    cudaGetSymbolAddress(&p_wv, g_Wvc);
    cudaGetSymbolAddress(&p_wo, g_Woc);

    cudaFuncSetAttribute(gemm_qkv_kernel, cudaFuncAttributeMaxDynamicSharedMemorySize, GEMM_SMEM);
    cudaFuncSetAttribute(gemm_out_kernel, cudaFuncAttributeMaxDynamicSharedMemorySize, GEMM_SMEM);
    cudaFuncSetAttribute(attn_mma_kernel, cudaFuncAttributeMaxDynamicSharedMemorySize, ATTN_SMEM);

    // pre-convert inputs + weights to tf32 bits
    cvt3_kernel<<<dim3(Mv * Dv / 1024, 3), 256>>>(
        (const float4*)q, (const float4*)k, (const float4*)v,
        (uint4*)p_qc, (uint4*)p_kc, (uint4*)p_vc, Mv * Dv / 4);
    cvt4_kernel<<<dim3(Dv * Dv / 1024, 4), 256>>>(
        (const float4*)Wq, (const float4*)Wk, (const float4*)Wv, (const float4*)Wo,
        (uint4*)p_wq, (uint4*)p_wk, (uint4*)p_wv, (uint4*)p_wo, Dv * Dv / 4);

    dim3 gQKV(Dv / 128, Mv / 128, 3);  // (6, 32, 3)
    gemm_qkv_kernel<<<gQKV, 128, GEMM_SMEM>>>(
        (const uint32_t*)p_qc, (const uint32_t*)p_kc, (const uint32_t*)p_vc,
        (const uint32_t*)p_wq, (const uint32_t*)p_wk, (const uint32_t*)p_wv,
        bq, bk, bv, (float*)p_qh, (float*)p_kh, (float*)p_vh);

    dim3 gAttn(Sv / 64, Bv * Hv);      // (32, 24)
    attn_mma_kernel<<<gAttn, 128, ATTN_SMEM>>>((const float*)p_qh, (const float*)p_kh,
                                               (const float*)p_vh, (float*)p_ctx);

    dim3 gGemm(Dv / 128, Mv / 128);    // (6, 32)
    gemm_out_kernel<<<gGemm, 128, GEMM_SMEM>>>(
        (const uint32_t*)p_ctx, (const uint32_t*)p_wo, bo, out);
}